// round 1
// baseline (speedup 1.0000x reference)
#include <cuda_runtime.h>
#include <cstdint>

// weight_quantize_fn: out = alpha * SF * q_kept * sign, with group-of-16 term budget.
// Plan: pass1 block partial sums (deterministic), pass2 finalize consts, pass3 quantize.

#define RED_BLOCKS 1184
#define RED_THREADS 256
#define QT 256

__device__ double g_psum[RED_BLOCKS];
__device__ double g_psq[RED_BLOCKS];
__device__ float  g_consts[4];   // [0]=scale=1/(std*alpha), [1]=bias=-mean*scale, [2]=C=SF*alpha

typedef unsigned long long u64;

// ---- packed f32x2 helpers (Blackwell) ----
__device__ __forceinline__ u64 pk2(float lo, float hi) {
    u64 r; asm("mov.b64 %0, {%1, %2};" : "=l"(r) : "f"(lo), "f"(hi)); return r;
}
__device__ __forceinline__ void upk2(u64 v, float& lo, float& hi) {
    asm("mov.b64 {%0, %1}, %2;" : "=f"(lo), "=f"(hi) : "l"(v));
}
__device__ __forceinline__ u64 ffma2(u64 a, u64 b, u64 c) {
    u64 d; asm("fma.rn.f32x2 %0, %1, %2, %3;" : "=l"(d) : "l"(a), "l"(b), "l"(c)); return d;
}
__device__ __forceinline__ u64 fadd2(u64 a, u64 b) {
    u64 d; asm("add.rn.f32x2 %0, %1, %2;" : "=l"(d) : "l"(a), "l"(b)); return d;
}
__device__ __forceinline__ u64 fmul2(u64 a, u64 b) {
    u64 d; asm("mul.rn.f32x2 %0, %1, %2;" : "=l"(d) : "l"(a), "l"(b)); return d;
}

// ---- pass 1: per-block partial sum / sumsq (deterministic order) ----
__global__ void reduce1(const float4* __restrict__ x, int nvec) {
    __shared__ double ss[RED_THREADS], sq[RED_THREADS];
    double s = 0.0, q = 0.0;
    int stride = gridDim.x * blockDim.x;
    for (int i = blockIdx.x * blockDim.x + threadIdx.x; i < nvec; i += stride) {
        float4 v = x[i];
        float a = (v.x + v.y) + (v.z + v.w);
        float b = (v.x * v.x + v.y * v.y) + (v.z * v.z + v.w * v.w);
        s += (double)a;
        q += (double)b;
    }
    ss[threadIdx.x] = s; sq[threadIdx.x] = q;
    __syncthreads();
    for (int o = RED_THREADS >> 1; o > 0; o >>= 1) {
        if (threadIdx.x < o) {
            ss[threadIdx.x] += ss[threadIdx.x + o];
            sq[threadIdx.x] += sq[threadIdx.x + o];
        }
        __syncthreads();
    }
    if (threadIdx.x == 0) { g_psum[blockIdx.x] = ss[0]; g_psq[blockIdx.x] = sq[0]; }
}

// ---- pass 2: finalize mean/std (ddof=1) and fold constants ----
__global__ void reduce2(const float* __restrict__ alpha_p, long long n) {
    __shared__ double ss[256], sq[256];
    double s = 0.0, q = 0.0;
    for (int i = threadIdx.x; i < RED_BLOCKS; i += 256) { s += g_psum[i]; q += g_psq[i]; }
    ss[threadIdx.x] = s; sq[threadIdx.x] = q;
    __syncthreads();
    for (int o = 128; o > 0; o >>= 1) {
        if (threadIdx.x < o) {
            ss[threadIdx.x] += ss[threadIdx.x + o];
            sq[threadIdx.x] += sq[threadIdx.x + o];
        }
        __syncthreads();
    }
    if (threadIdx.x == 0) {
        double N = (double)n;
        double mean = ss[0] / N;
        double var  = (sq[0] - N * mean * mean) / (N - 1.0);   // unbiased (ddof=1)
        double stdv = sqrt(var);
        double alpha = (double)(*alpha_p);
        double inv = 1.0 / (stdv * alpha);
        g_consts[0] = (float)inv;
        g_consts[1] = (float)(-mean * inv);
        g_consts[2] = (float)((double)(1.0f / 7.0f) * alpha);  // SF (fp32-rounded 1/7) * alpha
    }
}

// ---- pass 3: quantize, one thread per 16-element group ----
__global__ void __launch_bounds__(QT) quant(const float4* __restrict__ xv,
                                            float4* __restrict__ ov,
                                            const int* __restrict__ ntp, int ngroups) {
    int g = blockIdx.x * blockDim.x + threadIdx.x;
    if (g >= ngroups) return;

    float scale = g_consts[0], bias = g_consts[1], C = g_consts[2];
    const float MAGIC = 8388608.0f;               // 2^23: RN add == round-half-even to int
    u64 s2 = pk2(scale, scale);
    u64 b2 = pk2(bias, bias);
    u64 seven2  = pk2(7.0f, 7.0f);
    u64 magic2  = pk2(MAGIC, MAGIC);
    u64 nmagic2 = pk2(-MAGIC, -MAGIC);
    u64 C2 = pk2(C, C);

    float xs[16];
#pragma unroll
    for (int j = 0; j < 4; j++) {
        float4 v = xv[g * 4 + j];
        xs[j * 4 + 0] = v.x; xs[j * 4 + 1] = v.y; xs[j * 4 + 2] = v.z; xs[j * 4 + 3] = v.w;
    }

    float t[16], f[16];
#pragma unroll
    for (int p = 0; p < 8; p++) {
        u64 t2 = ffma2(pk2(xs[2 * p], xs[2 * p + 1]), s2, b2);  // t = x*scale + bias
        float tl, th; upk2(t2, tl, th);
        t[2 * p] = tl; t[2 * p + 1] = th;
        float al = fminf(fabsf(tl), 1.0f);                      // |clip(t)| — single FMNMX w/ |src|
        float ah = fminf(fabsf(th), 1.0f);
        u64 f2 = ffma2(pk2(al, ah), seven2, magic2);            // f = 2^23 + q, q=round_half_even(7a)
        upk2(f2, f[2 * p], f[2 * p + 1]);
    }

    // Sum of q's via integer adds of the raw float bits: low byte of sum == sum(q) (<=112).
    int qs = 0;
#pragma unroll
    for (int i = 0; i < 16; i++) qs += __float_as_int(f[i]);

    int budget = __ldg(ntp) * 16;   // num_terms * group_size

    float r[16];
    // popc(q) <= (q+1)/2 for q in [0,7]  =>  sum(q) <= 2*budget-16 guarantees total terms <= budget.
    if ((qs & 0xff) <= 2 * budget - 16) {
        // Fast path: every term kept -> qk == q.
#pragma unroll
        for (int p = 0; p < 8; p++) {
            u64 qf2 = fadd2(pk2(f[2 * p], f[2 * p + 1]), nmagic2);  // exact: qf = q as float
            u64 o2  = fmul2(qf2, C2);                               // |out| = q*SF*alpha
            float ol, oh; upk2(o2, ol, oh);
            r[2 * p]     = __int_as_float(__float_as_int(ol) | (__float_as_int(t[2 * p])     & 0x80000000));
            r[2 * p + 1] = __int_as_float(__float_as_int(oh) | (__float_as_int(t[2 * p + 1]) & 0x80000000));
        }
    } else {
        // Exact path (astronomically rare for num_terms=2): stable descending term sort semantics.
        // All 4-terms ordered by element index come first, then 2-terms, then 1-terms.
        int m1 = 0, m2 = 0, m4 = 0;
#pragma unroll
        for (int i = 0; i < 16; i++) {
            int q = __float_as_int(f[i]) & 7;
            m1 |= (q & 1) << i;
            m2 |= ((q >> 1) & 1) << i;
            m4 |= ((q >> 2) & 1) << i;
        }
        int c4 = min(__popc(m4), budget);
        int rem = budget - c4;
        int c2 = min(__popc(m2), rem); rem -= c2;
        int c1 = min(__popc(m1), rem);
        if (c1 < 0) c1 = 0;
#pragma unroll
        for (int i = 0; i < 16; i++) {
            int below = (1 << i) - 1;
            int k4 = ((m4 >> i) & 1) & ((__popc(m4 & below) < c4) ? 1 : 0);
            int k2 = ((m2 >> i) & 1) & ((__popc(m2 & below) < c2) ? 1 : 0);
            int k1 = ((m1 >> i) & 1) & ((__popc(m1 & below) < c1) ? 1 : 0);
            int kept = (k4 << 2) | (k2 << 1) | k1;
            float o = (float)kept * C;
            r[i] = __int_as_float(__float_as_int(o) | (__float_as_int(t[i]) & 0x80000000));
        }
    }

#pragma unroll
    for (int j = 0; j < 4; j++) {
        float4 w;
        w.x = r[j * 4 + 0]; w.y = r[j * 4 + 1]; w.z = r[j * 4 + 2]; w.w = r[j * 4 + 3];
        ov[g * 4 + j] = w;
    }
}

extern "C" void kernel_launch(void* const* d_in, const int* in_sizes, int n_in,
                              void* d_out, int out_size) {
    const float* w     = (const float*)d_in[0];
    const float* alpha = (const float*)d_in[1];
    const int*   nt    = (const int*)d_in[2];
    int n = in_sizes[0];
    int nvec = n / 4;
    int ngroups = n / 16;

    reduce1<<<RED_BLOCKS, RED_THREADS>>>((const float4*)w, nvec);
    reduce2<<<1, 256>>>(alpha, (long long)n);
    int qb = (ngroups + QT - 1) / QT;
    quant<<<qb, QT>>>((const float4*)w, (float4*)d_out, nt, ngroups);
}

// round 2
// speedup vs baseline: 1.4073x; 1.4073x over previous
#include <cuda_runtime.h>
#include <cstdint>

// weight_quantize_fn: out = alpha * SF * q_kept * sign, with group-of-16 term budget.
// R2: reduce1 hot loop is pure fp32 (FP64 pipe was pacing it at 22% DRAM);
//     promote to double once per thread. quant uses streaming stores to keep
//     the input resident in L2 between passes.

#define RED_BLOCKS 1184
#define RED_THREADS 256
#define QT 256

__device__ double g_psum[RED_BLOCKS];
__device__ double g_psq[RED_BLOCKS];
__device__ float  g_consts[4];   // [0]=scale=1/(std*alpha), [1]=bias=-mean*scale, [2]=C=SF*alpha

typedef unsigned long long u64;

// ---- packed f32x2 helpers (Blackwell) ----
__device__ __forceinline__ u64 pk2(float lo, float hi) {
    u64 r; asm("mov.b64 %0, {%1, %2};" : "=l"(r) : "f"(lo), "f"(hi)); return r;
}
__device__ __forceinline__ void upk2(u64 v, float& lo, float& hi) {
    asm("mov.b64 {%0, %1}, %2;" : "=f"(lo), "=f"(hi) : "l"(v));
}
__device__ __forceinline__ u64 ffma2(u64 a, u64 b, u64 c) {
    u64 d; asm("fma.rn.f32x2 %0, %1, %2, %3;" : "=l"(d) : "l"(a), "l"(b), "l"(c)); return d;
}
__device__ __forceinline__ u64 fadd2(u64 a, u64 b) {
    u64 d; asm("add.rn.f32x2 %0, %1, %2;" : "=l"(d) : "l"(a), "l"(b)); return d;
}
__device__ __forceinline__ u64 fmul2(u64 a, u64 b) {
    u64 d; asm("mul.rn.f32x2 %0, %1, %2;" : "=l"(d) : "l"(a), "l"(b)); return d;
}

__device__ __forceinline__ void stcs4(float4* p, float4 v) {
    asm volatile("st.global.cs.v4.f32 [%0], {%1, %2, %3, %4};"
                 :: "l"(p), "f"(v.x), "f"(v.y), "f"(v.z), "f"(v.w) : "memory");
}

// ---- pass 1: per-block partial sum / sumsq; fp32 hot loop, double only at the end ----
__global__ void reduce1(const float4* __restrict__ x, int nvec) {
    __shared__ double ss[RED_THREADS], sq[RED_THREADS];
    float s0 = 0.f, s1 = 0.f, q0 = 0.f, q1 = 0.f;   // 2 independent chains for ILP
    int stride = gridDim.x * blockDim.x;
    int i = blockIdx.x * blockDim.x + threadIdx.x;
    for (; i + stride < nvec; i += 2 * stride) {
        float4 a = x[i];
        float4 b = x[i + stride];
        s0 += (a.x + a.y) + (a.z + a.w);
        q0 += (a.x * a.x + a.y * a.y) + (a.z * a.z + a.w * a.w);
        s1 += (b.x + b.y) + (b.z + b.w);
        q1 += (b.x * b.x + b.y * b.y) + (b.z * b.z + b.w * b.w);
    }
    if (i < nvec) {
        float4 a = x[i];
        s0 += (a.x + a.y) + (a.z + a.w);
        q0 += (a.x * a.x + a.y * a.y) + (a.z * a.z + a.w * a.w);
    }
    ss[threadIdx.x] = (double)s0 + (double)s1;
    sq[threadIdx.x] = (double)q0 + (double)q1;
    __syncthreads();
    for (int o = RED_THREADS >> 1; o > 0; o >>= 1) {
        if (threadIdx.x < o) {
            ss[threadIdx.x] += ss[threadIdx.x + o];
            sq[threadIdx.x] += sq[threadIdx.x + o];
        }
        __syncthreads();
    }
    if (threadIdx.x == 0) { g_psum[blockIdx.x] = ss[0]; g_psq[blockIdx.x] = sq[0]; }
}

// ---- pass 2: finalize mean/std (ddof=1) and fold constants ----
__global__ void reduce2(const float* __restrict__ alpha_p, long long n) {
    __shared__ double ss[256], sq[256];
    double s = 0.0, q = 0.0;
    for (int i = threadIdx.x; i < RED_BLOCKS; i += 256) { s += g_psum[i]; q += g_psq[i]; }
    ss[threadIdx.x] = s; sq[threadIdx.x] = q;
    __syncthreads();
    for (int o = 128; o > 0; o >>= 1) {
        if (threadIdx.x < o) {
            ss[threadIdx.x] += ss[threadIdx.x + o];
            sq[threadIdx.x] += sq[threadIdx.x + o];
        }
        __syncthreads();
    }
    if (threadIdx.x == 0) {
        double N = (double)n;
        double mean = ss[0] / N;
        double var  = (sq[0] - N * mean * mean) / (N - 1.0);   // unbiased (ddof=1)
        double stdv = sqrt(var);
        double alpha = (double)(*alpha_p);
        double inv = 1.0 / (stdv * alpha);
        g_consts[0] = (float)inv;
        g_consts[1] = (float)(-mean * inv);
        g_consts[2] = (float)((double)(1.0f / 7.0f) * alpha);  // SF (fp32-rounded 1/7) * alpha
    }
}

// ---- pass 3: quantize, one thread per 16-element group ----
__global__ void __launch_bounds__(QT) quant(const float4* __restrict__ xv,
                                            float4* __restrict__ ov,
                                            const int* __restrict__ ntp, int ngroups) {
    int g = blockIdx.x * blockDim.x + threadIdx.x;
    if (g >= ngroups) return;

    float scale = g_consts[0], bias = g_consts[1], C = g_consts[2];
    const float MAGIC = 8388608.0f;               // 2^23: RN add == round-half-even to int
    u64 s2 = pk2(scale, scale);
    u64 b2 = pk2(bias, bias);
    u64 seven2  = pk2(7.0f, 7.0f);
    u64 magic2  = pk2(MAGIC, MAGIC);
    u64 nmagic2 = pk2(-MAGIC, -MAGIC);
    u64 C2 = pk2(C, C);

    float xs[16];
#pragma unroll
    for (int j = 0; j < 4; j++) {
        float4 v = xv[g * 4 + j];
        xs[j * 4 + 0] = v.x; xs[j * 4 + 1] = v.y; xs[j * 4 + 2] = v.z; xs[j * 4 + 3] = v.w;
    }

    float t[16], f[16];
#pragma unroll
    for (int p = 0; p < 8; p++) {
        u64 t2 = ffma2(pk2(xs[2 * p], xs[2 * p + 1]), s2, b2);  // t = x*scale + bias
        float tl, th; upk2(t2, tl, th);
        t[2 * p] = tl; t[2 * p + 1] = th;
        float al = fminf(fabsf(tl), 1.0f);                      // |clip(t)| — FMNMX with |src|
        float ah = fminf(fabsf(th), 1.0f);
        u64 f2 = ffma2(pk2(al, ah), seven2, magic2);            // f = 2^23 + q, q=round_half_even(7a)
        upk2(f2, f[2 * p], f[2 * p + 1]);
    }

    // Sum of q's via integer adds of the raw float bits: low byte of sum == sum(q) (<=112).
    int qs = 0;
#pragma unroll
    for (int i = 0; i < 16; i++) qs += __float_as_int(f[i]);

    int budget = __ldg(ntp) * 16;   // num_terms * group_size

    float r[16];
    // popc(q) <= (q+1)/2 for q in [0,7]  =>  sum(q) <= 2*budget-16 guarantees total terms <= budget.
    if ((qs & 0xff) <= 2 * budget - 16) {
        // Fast path: every term kept -> qk == q.
#pragma unroll
        for (int p = 0; p < 8; p++) {
            u64 qf2 = fadd2(pk2(f[2 * p], f[2 * p + 1]), nmagic2);  // exact: qf = q as float
            u64 o2  = fmul2(qf2, C2);                               // |out| = q*SF*alpha
            float ol, oh; upk2(o2, ol, oh);
            r[2 * p]     = __int_as_float(__float_as_int(ol) | (__float_as_int(t[2 * p])     & 0x80000000));
            r[2 * p + 1] = __int_as_float(__float_as_int(oh) | (__float_as_int(t[2 * p + 1]) & 0x80000000));
        }
    } else {
        // Exact path (astronomically rare for num_terms=2): stable descending term sort semantics.
        // All 4-terms ordered by element index come first, then 2-terms, then 1-terms.
        int m1 = 0, m2 = 0, m4 = 0;
#pragma unroll
        for (int i = 0; i < 16; i++) {
            int q = __float_as_int(f[i]) & 7;
            m1 |= (q & 1) << i;
            m2 |= ((q >> 1) & 1) << i;
            m4 |= ((q >> 2) & 1) << i;
        }
        int c4 = min(__popc(m4), budget);
        int rem = budget - c4;
        int c2 = min(__popc(m2), rem); rem -= c2;
        int c1 = min(__popc(m1), rem);
        if (c1 < 0) c1 = 0;
#pragma unroll
        for (int i = 0; i < 16; i++) {
            int below = (1 << i) - 1;
            int k4 = ((m4 >> i) & 1) & ((__popc(m4 & below) < c4) ? 1 : 0);
            int k2 = ((m2 >> i) & 1) & ((__popc(m2 & below) < c2) ? 1 : 0);
            int k1 = ((m1 >> i) & 1) & ((__popc(m1 & below) < c1) ? 1 : 0);
            int kept = (k4 << 2) | (k2 << 1) | k1;
            float o = (float)kept * C;
            r[i] = __int_as_float(__float_as_int(o) | (__float_as_int(t[i]) & 0x80000000));
        }
    }

#pragma unroll
    for (int j = 0; j < 4; j++) {
        float4 w;
        w.x = r[j * 4 + 0]; w.y = r[j * 4 + 1]; w.z = r[j * 4 + 2]; w.w = r[j * 4 + 3];
        stcs4(&ov[g * 4 + j], w);   // streaming store: don't evict input from L2
    }
}

extern "C" void kernel_launch(void* const* d_in, const int* in_sizes, int n_in,
                              void* d_out, int out_size) {
    const float* w     = (const float*)d_in[0];
    const float* alpha = (const float*)d_in[1];
    const int*   nt    = (const int*)d_in[2];
    int n = in_sizes[0];
    int nvec = n / 4;
    int ngroups = n / 16;

    reduce1<<<RED_BLOCKS, RED_THREADS>>>((const float4*)w, nvec);
    reduce2<<<1, 256>>>(alpha, (long long)n);
    int qb = (ngroups + QT - 1) / QT;
    quant<<<qb, QT>>>((const float4*)w, (float4*)d_out, nt, ngroups);
}

// round 3
// speedup vs baseline: 1.5860x; 1.1270x over previous
#include <cuda_runtime.h>
#include <cstdint>

// weight_quantize_fn: out = alpha * SF * q_kept * sign, with group-of-16 term budget.
// R3: reduce1 with 4 independent load chains (MLP 2->4);
//     quant re-parallelized to one float4/thread (coalesced LDG/STG) with
//     4-lane-cluster cooperation for the group budget via shfl;
//     quant runs in reverse block order to hit the L2-resident tail left by reduce1.

#define RED_BLOCKS 1184
#define RED_THREADS 256
#define QT 256

__device__ double g_psum[RED_BLOCKS];
__device__ double g_psq[RED_BLOCKS];
__device__ float  g_consts[4];   // [0]=scale=1/(std*alpha), [1]=bias=-mean*scale, [2]=C=SF*alpha

typedef unsigned long long u64;

// ---- packed f32x2 helpers (Blackwell) ----
__device__ __forceinline__ u64 pk2(float lo, float hi) {
    u64 r; asm("mov.b64 %0, {%1, %2};" : "=l"(r) : "f"(lo), "f"(hi)); return r;
}
__device__ __forceinline__ void upk2(u64 v, float& lo, float& hi) {
    asm("mov.b64 {%0, %1}, %2;" : "=f"(lo), "=f"(hi) : "l"(v));
}
__device__ __forceinline__ u64 ffma2(u64 a, u64 b, u64 c) {
    u64 d; asm("fma.rn.f32x2 %0, %1, %2, %3;" : "=l"(d) : "l"(a), "l"(b), "l"(c)); return d;
}
__device__ __forceinline__ u64 fadd2(u64 a, u64 b) {
    u64 d; asm("add.rn.f32x2 %0, %1, %2;" : "=l"(d) : "l"(a), "l"(b)); return d;
}
__device__ __forceinline__ u64 fmul2(u64 a, u64 b) {
    u64 d; asm("mul.rn.f32x2 %0, %1, %2;" : "=l"(d) : "l"(a), "l"(b)); return d;
}

__device__ __forceinline__ void stcs4(float4* p, float4 v) {
    asm volatile("st.global.cs.v4.f32 [%0], {%1, %2, %3, %4};"
                 :: "l"(p), "f"(v.x), "f"(v.y), "f"(v.z), "f"(v.w) : "memory");
}

// ---- pass 1: per-block partial sum / sumsq; fp32 hot loop, 4 chains for MLP ----
__global__ void reduce1(const float4* __restrict__ x, int nvec) {
    __shared__ double ss[RED_THREADS], sq[RED_THREADS];
    float s0 = 0.f, s1 = 0.f, s2 = 0.f, s3 = 0.f;
    float q0 = 0.f, q1 = 0.f, q2 = 0.f, q3 = 0.f;
    int stride = gridDim.x * blockDim.x;
    int i = blockIdx.x * blockDim.x + threadIdx.x;
    for (; i + 3 * stride < nvec; i += 4 * stride) {
        float4 a = x[i];
        float4 b = x[i + stride];
        float4 c = x[i + 2 * stride];
        float4 d = x[i + 3 * stride];
        s0 += (a.x + a.y) + (a.z + a.w);
        q0 += (a.x * a.x + a.y * a.y) + (a.z * a.z + a.w * a.w);
        s1 += (b.x + b.y) + (b.z + b.w);
        q1 += (b.x * b.x + b.y * b.y) + (b.z * b.z + b.w * b.w);
        s2 += (c.x + c.y) + (c.z + c.w);
        q2 += (c.x * c.x + c.y * c.y) + (c.z * c.z + c.w * c.w);
        s3 += (d.x + d.y) + (d.z + d.w);
        q3 += (d.x * d.x + d.y * d.y) + (d.z * d.z + d.w * d.w);
    }
    for (; i < nvec; i += stride) {
        float4 a = x[i];
        s0 += (a.x + a.y) + (a.z + a.w);
        q0 += (a.x * a.x + a.y * a.y) + (a.z * a.z + a.w * a.w);
    }
    ss[threadIdx.x] = ((double)s0 + (double)s1) + ((double)s2 + (double)s3);
    sq[threadIdx.x] = ((double)q0 + (double)q1) + ((double)q2 + (double)q3);
    __syncthreads();
    for (int o = RED_THREADS >> 1; o > 0; o >>= 1) {
        if (threadIdx.x < o) {
            ss[threadIdx.x] += ss[threadIdx.x + o];
            sq[threadIdx.x] += sq[threadIdx.x + o];
        }
        __syncthreads();
    }
    if (threadIdx.x == 0) { g_psum[blockIdx.x] = ss[0]; g_psq[blockIdx.x] = sq[0]; }
}

// ---- pass 2: finalize mean/std (ddof=1) and fold constants ----
__global__ void reduce2(const float* __restrict__ alpha_p, long long n) {
    __shared__ double ss[256], sq[256];
    double s = 0.0, q = 0.0;
    for (int i = threadIdx.x; i < RED_BLOCKS; i += 256) { s += g_psum[i]; q += g_psq[i]; }
    ss[threadIdx.x] = s; sq[threadIdx.x] = q;
    __syncthreads();
    for (int o = 128; o > 0; o >>= 1) {
        if (threadIdx.x < o) {
            ss[threadIdx.x] += ss[threadIdx.x + o];
            sq[threadIdx.x] += sq[threadIdx.x + o];
        }
        __syncthreads();
    }
    if (threadIdx.x == 0) {
        double N = (double)n;
        double mean = ss[0] / N;
        double var  = (sq[0] - N * mean * mean) / (N - 1.0);   // unbiased (ddof=1)
        double stdv = sqrt(var);
        double alpha = (double)(*alpha_p);
        double inv = 1.0 / (stdv * alpha);
        g_consts[0] = (float)inv;
        g_consts[1] = (float)(-mean * inv);
        g_consts[2] = (float)((double)(1.0f / 7.0f) * alpha);  // SF (fp32-rounded 1/7) * alpha
    }
}

// ---- pass 3: quantize. One float4 per thread; 4-lane clusters own one group of 16. ----
__global__ void __launch_bounds__(QT) quant(const float4* __restrict__ xv,
                                            float4* __restrict__ ov,
                                            const int* __restrict__ ntp, int nvec) {
    // Reverse block order: consume the L2-resident tail left by reduce1 first.
    int rb = gridDim.x - 1 - blockIdx.x;
    int idx = rb * blockDim.x + threadIdx.x;
    if (idx >= nvec) return;

    float scale = g_consts[0], bias = g_consts[1], C = g_consts[2];
    const float MAGIC = 8388608.0f;               // 2^23: RN add == round-half-even to int
    u64 s2 = pk2(scale, scale);
    u64 b2 = pk2(bias, bias);
    u64 seven2  = pk2(7.0f, 7.0f);
    u64 magic2  = pk2(MAGIC, MAGIC);
    u64 nmagic2 = pk2(-MAGIC, -MAGIC);
    u64 C2 = pk2(C, C);

    float4 v = xv[idx];                           // fully coalesced
    float X[4] = {v.x, v.y, v.z, v.w};

    float t[4], f[4];
#pragma unroll
    for (int p = 0; p < 2; p++) {
        u64 t2 = ffma2(pk2(X[2 * p], X[2 * p + 1]), s2, b2);    // t = x*scale + bias
        upk2(t2, t[2 * p], t[2 * p + 1]);
        float al = fminf(fabsf(t[2 * p]), 1.0f);                // |clip(t)| — FMNMX with |src|
        float ah = fminf(fabsf(t[2 * p + 1]), 1.0f);
        u64 f2 = ffma2(pk2(al, ah), seven2, magic2);            // f = 2^23 + q (round-half-even)
        upk2(f2, f[2 * p], f[2 * p + 1]);
    }

    // Group sum of q over the 16 elements owned by this 4-lane cluster.
    // Low byte of the int-bit sum == sum(q) (<=112); magic exponent bits don't touch it.
    int qs = __float_as_int(f[0]) + __float_as_int(f[1]) +
             __float_as_int(f[2]) + __float_as_int(f[3]);
    qs += __shfl_xor_sync(0xffffffffu, qs, 1);
    qs += __shfl_xor_sync(0xffffffffu, qs, 2);

    int budget = __ldg(ntp) * 16;                 // num_terms * group_size

    float4 w;
    float* r = &w.x;
    // popc(q) <= (q+1)/2 for q in [0,7]  =>  sum(q) <= 2*budget-16 guarantees terms <= budget.
    if ((qs & 0xff) <= 2 * budget - 16) {
        // Fast path: every term kept -> qk == q.
#pragma unroll
        for (int p = 0; p < 2; p++) {
            u64 qf2 = fadd2(pk2(f[2 * p], f[2 * p + 1]), nmagic2);  // exact: qf = q as float
            u64 o2  = fmul2(qf2, C2);                               // |out| = q*SF*alpha
            float ol, oh; upk2(o2, ol, oh);
            r[2 * p]     = __int_as_float(__float_as_int(ol) | (__float_as_int(t[2 * p])     & 0x80000000));
            r[2 * p + 1] = __int_as_float(__float_as_int(oh) | (__float_as_int(t[2 * p + 1]) & 0x80000000));
        }
    } else {
        // Exact path (rare): stable-descending-sort semantics.
        // Assemble full 16-bit group masks across the 4-lane cluster.
        int lane = threadIdx.x & 31;
        unsigned cmask = 0xFu << (lane & ~3);     // the 4 lanes of this cluster
        int pos = (lane & 3) * 4;                 // this lane's element offset in the group
        int m1 = 0, m2 = 0, m4 = 0;
#pragma unroll
        for (int k = 0; k < 4; k++) {
            int q = __float_as_int(f[k]) & 7;
            m1 |= (q & 1) << (pos + k);
            m2 |= ((q >> 1) & 1) << (pos + k);
            m4 |= ((q >> 2) & 1) << (pos + k);
        }
        m1 |= __shfl_xor_sync(cmask, m1, 1);  m1 |= __shfl_xor_sync(cmask, m1, 2);
        m2 |= __shfl_xor_sync(cmask, m2, 1);  m2 |= __shfl_xor_sync(cmask, m2, 2);
        m4 |= __shfl_xor_sync(cmask, m4, 1);  m4 |= __shfl_xor_sync(cmask, m4, 2);
        int c4 = min(__popc(m4), budget);
        int rem = budget - c4;
        int c2 = min(__popc(m2), rem); rem -= c2;
        int c1 = min(__popc(m1), rem);
        if (c1 < 0) c1 = 0;
#pragma unroll
        for (int k = 0; k < 4; k++) {
            int i16 = pos + k;
            int below = (1 << i16) - 1;
            int k4 = ((m4 >> i16) & 1) & ((__popc(m4 & below) < c4) ? 1 : 0);
            int k2 = ((m2 >> i16) & 1) & ((__popc(m2 & below) < c2) ? 1 : 0);
            int k1 = ((m1 >> i16) & 1) & ((__popc(m1 & below) < c1) ? 1 : 0);
            int kept = (k4 << 2) | (k2 << 1) | k1;
            float o = (float)kept * C;
            r[k] = __int_as_float(__float_as_int(o) | (__float_as_int(t[k]) & 0x80000000));
        }
    }

    stcs4(&ov[idx], w);                           // coalesced streaming store
}

extern "C" void kernel_launch(void* const* d_in, const int* in_sizes, int n_in,
                              void* d_out, int out_size) {
    const float* w     = (const float*)d_in[0];
    const float* alpha = (const float*)d_in[1];
    const int*   nt    = (const int*)d_in[2];
    int n = in_sizes[0];
    int nvec = n / 4;

    reduce1<<<RED_BLOCKS, RED_THREADS>>>((const float4*)w, nvec);
    reduce2<<<1, 256>>>(alpha, (long long)n);
    int qb = (nvec + QT - 1) / QT;
    quant<<<qb, QT>>>((const float4*)w, (float4*)d_out, nt, nvec);
}

// round 4
// speedup vs baseline: 1.6559x; 1.0441x over previous
#include <cuda_runtime.h>
#include <cstdint>

// weight_quantize_fn: out = alpha * SF * q_kept * sign, with group-of-16 term budget.
// R4: reduce1 made block-contiguous (each CTA streams one 128KB chunk; the 6.6TB/s
//     quant kernel proves this address pattern is what the memory system likes)
//     and reduce2 fused in via last-block finalize (threadfence+atomicInc).

#define RT 256
#define VPT 32                 // float4 per thread
#define BCHUNK (RT * VPT)      // 8192 float4 = 128KB per block chunk
#define MAXB 8192
#define QT 256

__device__ double g_psum[MAXB];
__device__ double g_psq[MAXB];
__device__ float  g_consts[4];   // [0]=scale=1/(std*alpha), [1]=bias=-mean*scale, [2]=C=SF*alpha
__device__ unsigned g_count;     // zero-init; wraps back to 0 every launch (graph-replay safe)

typedef unsigned long long u64;

// ---- packed f32x2 helpers (Blackwell) ----
__device__ __forceinline__ u64 pk2(float lo, float hi) {
    u64 r; asm("mov.b64 %0, {%1, %2};" : "=l"(r) : "f"(lo), "f"(hi)); return r;
}
__device__ __forceinline__ void upk2(u64 v, float& lo, float& hi) {
    asm("mov.b64 {%0, %1}, %2;" : "=f"(lo), "=f"(hi) : "l"(v));
}
__device__ __forceinline__ u64 ffma2(u64 a, u64 b, u64 c) {
    u64 d; asm("fma.rn.f32x2 %0, %1, %2, %3;" : "=l"(d) : "l"(a), "l"(b), "l"(c)); return d;
}
__device__ __forceinline__ u64 fadd2(u64 a, u64 b) {
    u64 d; asm("add.rn.f32x2 %0, %1, %2;" : "=l"(d) : "l"(a), "l"(b)); return d;
}
__device__ __forceinline__ u64 fmul2(u64 a, u64 b) {
    u64 d; asm("mul.rn.f32x2 %0, %1, %2;" : "=l"(d) : "l"(a), "l"(b)); return d;
}
__device__ __forceinline__ void stcs4(float4* p, float4 v) {
    asm volatile("st.global.cs.v4.f32 [%0], {%1, %2, %3, %4};"
                 :: "l"(p), "f"(v.x), "f"(v.y), "f"(v.z), "f"(v.w) : "memory");
}

// ---- pass 1: block-contiguous partial sums + fused finalize ----
__global__ void __launch_bounds__(RT) reduce1(const float4* __restrict__ x,
                                              const float* __restrict__ alpha_p,
                                              int nvec, int nchunks, long long n) {
    __shared__ double ss[RT], sq[RT];
    __shared__ bool is_last;
    float s0 = 0.f, s1 = 0.f, s2 = 0.f, s3 = 0.f;
    float q0 = 0.f, q1 = 0.f, q2 = 0.f, q3 = 0.f;

    // Each block streams contiguous 128KB chunks (stride gridDim.x over chunks).
    for (int ch = blockIdx.x; ch < nchunks; ch += gridDim.x) {
        int i = ch * BCHUNK + threadIdx.x;
#pragma unroll
        for (int it = 0; it < VPT / 4; it++) {
            float4 a = x[i];
            float4 b = x[i + RT];
            float4 c = x[i + 2 * RT];
            float4 d = x[i + 3 * RT];
            s0 += (a.x + a.y) + (a.z + a.w);
            q0 += (a.x * a.x + a.y * a.y) + (a.z * a.z + a.w * a.w);
            s1 += (b.x + b.y) + (b.z + b.w);
            q1 += (b.x * b.x + b.y * b.y) + (b.z * b.z + b.w * b.w);
            s2 += (c.x + c.y) + (c.z + c.w);
            q2 += (c.x * c.x + c.y * c.y) + (c.z * c.z + c.w * c.w);
            s3 += (d.x + d.y) + (d.z + d.w);
            q3 += (d.x * d.x + d.y * d.y) + (d.z * d.z + d.w * d.w);
            i += 4 * RT;
        }
    }
    // Remainder (nvec not multiple of BCHUNK): block 0 mops up.
    if (blockIdx.x == 0) {
        for (int i = nchunks * BCHUNK + threadIdx.x; i < nvec; i += RT) {
            float4 a = x[i];
            s0 += (a.x + a.y) + (a.z + a.w);
            q0 += (a.x * a.x + a.y * a.y) + (a.z * a.z + a.w * a.w);
        }
    }

    ss[threadIdx.x] = ((double)s0 + (double)s1) + ((double)s2 + (double)s3);
    sq[threadIdx.x] = ((double)q0 + (double)q1) + ((double)q2 + (double)q3);
    __syncthreads();
    for (int o = RT >> 1; o > 0; o >>= 1) {
        if (threadIdx.x < o) {
            ss[threadIdx.x] += ss[threadIdx.x + o];
            sq[threadIdx.x] += sq[threadIdx.x + o];
        }
        __syncthreads();
    }
    if (threadIdx.x == 0) { g_psum[blockIdx.x] = ss[0]; g_psq[blockIdx.x] = sq[0]; }

    // Last-block finalize (threadFenceReduction pattern; deterministic order).
    __threadfence();
    if (threadIdx.x == 0) {
        unsigned c = atomicInc(&g_count, gridDim.x - 1);   // wraps to 0 for next launch
        is_last = (c == gridDim.x - 1);
    }
    __syncthreads();
    if (is_last) {
        double s = 0.0, q = 0.0;
        for (int i = threadIdx.x; i < gridDim.x; i += RT) { s += g_psum[i]; q += g_psq[i]; }
        ss[threadIdx.x] = s; sq[threadIdx.x] = q;
        __syncthreads();
        for (int o = RT >> 1; o > 0; o >>= 1) {
            if (threadIdx.x < o) {
                ss[threadIdx.x] += ss[threadIdx.x + o];
                sq[threadIdx.x] += sq[threadIdx.x + o];
            }
            __syncthreads();
        }
        if (threadIdx.x == 0) {
            double N = (double)n;
            double mean = ss[0] / N;
            double var  = (sq[0] - N * mean * mean) / (N - 1.0);   // unbiased (ddof=1)
            double stdv = sqrt(var);
            double alpha = (double)(*alpha_p);
            double inv = 1.0 / (stdv * alpha);
            g_consts[0] = (float)inv;
            g_consts[1] = (float)(-mean * inv);
            g_consts[2] = (float)((double)(1.0f / 7.0f) * alpha);  // SF (fp32 1/7) * alpha
        }
    }
}

// ---- pass 2: quantize. One float4 per thread; 4-lane clusters own one group of 16. ----
__global__ void __launch_bounds__(QT) quant(const float4* __restrict__ xv,
                                            float4* __restrict__ ov,
                                            const int* __restrict__ ntp, int nvec) {
    // Reverse block order: consume the L2-resident tail left by reduce1 first.
    int rb = gridDim.x - 1 - blockIdx.x;
    int idx = rb * blockDim.x + threadIdx.x;
    if (idx >= nvec) return;

    float scale = g_consts[0], bias = g_consts[1], C = g_consts[2];
    const float MAGIC = 8388608.0f;               // 2^23: RN add == round-half-even to int
    u64 s2 = pk2(scale, scale);
    u64 b2 = pk2(bias, bias);
    u64 seven2  = pk2(7.0f, 7.0f);
    u64 magic2  = pk2(MAGIC, MAGIC);
    u64 nmagic2 = pk2(-MAGIC, -MAGIC);
    u64 C2 = pk2(C, C);

    float4 v = xv[idx];                           // fully coalesced
    float X[4] = {v.x, v.y, v.z, v.w};

    float t[4], f[4];
#pragma unroll
    for (int p = 0; p < 2; p++) {
        u64 t2 = ffma2(pk2(X[2 * p], X[2 * p + 1]), s2, b2);    // t = x*scale + bias
        upk2(t2, t[2 * p], t[2 * p + 1]);
        float al = fminf(fabsf(t[2 * p]), 1.0f);                // |clip(t)| — FMNMX with |src|
        float ah = fminf(fabsf(t[2 * p + 1]), 1.0f);
        u64 f2 = ffma2(pk2(al, ah), seven2, magic2);            // f = 2^23 + q (round-half-even)
        upk2(f2, f[2 * p], f[2 * p + 1]);
    }

    // Group sum of q over the 16 elements owned by this 4-lane cluster.
    int qs = __float_as_int(f[0]) + __float_as_int(f[1]) +
             __float_as_int(f[2]) + __float_as_int(f[3]);
    qs += __shfl_xor_sync(0xffffffffu, qs, 1);
    qs += __shfl_xor_sync(0xffffffffu, qs, 2);

    int budget = __ldg(ntp) * 16;                 // num_terms * group_size

    float4 w;
    float* r = &w.x;
    // popc(q) <= (q+1)/2 for q in [0,7]  =>  sum(q) <= 2*budget-16 guarantees terms <= budget.
    if ((qs & 0xff) <= 2 * budget - 16) {
        // Fast path: every term kept -> qk == q.
#pragma unroll
        for (int p = 0; p < 2; p++) {
            u64 qf2 = fadd2(pk2(f[2 * p], f[2 * p + 1]), nmagic2);  // exact: qf = q as float
            u64 o2  = fmul2(qf2, C2);                               // |out| = q*SF*alpha
            float ol, oh; upk2(o2, ol, oh);
            r[2 * p]     = __int_as_float(__float_as_int(ol) | (__float_as_int(t[2 * p])     & 0x80000000));
            r[2 * p + 1] = __int_as_float(__float_as_int(oh) | (__float_as_int(t[2 * p + 1]) & 0x80000000));
        }
    } else {
        // Exact path (rare): stable-descending-sort semantics.
        int lane = threadIdx.x & 31;
        unsigned cmask = 0xFu << (lane & ~3);     // the 4 lanes of this cluster
        int pos = (lane & 3) * 4;                 // this lane's element offset in the group
        int m1 = 0, m2 = 0, m4 = 0;
#pragma unroll
        for (int k = 0; k < 4; k++) {
            int q = __float_as_int(f[k]) & 7;
            m1 |= (q & 1) << (pos + k);
            m2 |= ((q >> 1) & 1) << (pos + k);
            m4 |= ((q >> 2) & 1) << (pos + k);
        }
        m1 |= __shfl_xor_sync(cmask, m1, 1);  m1 |= __shfl_xor_sync(cmask, m1, 2);
        m2 |= __shfl_xor_sync(cmask, m2, 1);  m2 |= __shfl_xor_sync(cmask, m2, 2);
        m4 |= __shfl_xor_sync(cmask, m4, 1);  m4 |= __shfl_xor_sync(cmask, m4, 2);
        int c4 = min(__popc(m4), budget);
        int rem = budget - c4;
        int c2 = min(__popc(m2), rem); rem -= c2;
        int c1 = min(__popc(m1), rem);
        if (c1 < 0) c1 = 0;
#pragma unroll
        for (int k = 0; k < 4; k++) {
            int i16 = pos + k;
            int below = (1 << i16) - 1;
            int k4 = ((m4 >> i16) & 1) & ((__popc(m4 & below) < c4) ? 1 : 0);
            int k2 = ((m2 >> i16) & 1) & ((__popc(m2 & below) < c2) ? 1 : 0);
            int k1 = ((m1 >> i16) & 1) & ((__popc(m1 & below) < c1) ? 1 : 0);
            int kept = (k4 << 2) | (k2 << 1) | k1;
            float o = (float)kept * C;
            r[k] = __int_as_float(__float_as_int(o) | (__float_as_int(t[k]) & 0x80000000));
        }
    }

    stcs4(&ov[idx], w);                           // coalesced streaming store
}

extern "C" void kernel_launch(void* const* d_in, const int* in_sizes, int n_in,
                              void* d_out, int out_size) {
    const float* w     = (const float*)d_in[0];
    const float* alpha = (const float*)d_in[1];
    const int*   nt    = (const int*)d_in[2];
    int n = in_sizes[0];
    int nvec = n / 4;

    int nchunks = nvec / BCHUNK;                 // 1024 for 4096x8192
    int nb = nchunks < 1 ? 1 : (nchunks > MAXB ? MAXB : nchunks);

    reduce1<<<nb, RT>>>((const float4*)w, alpha, nvec, nchunks, (long long)n);
    int qb = (nvec + QT - 1) / QT;
    quant<<<qb, QT>>>((const float4*)w, (float4*)d_out, nt, nvec);
}